// round 2
// baseline (speedup 1.0000x reference)
#include <cuda_runtime.h>
#include <cuda_bf16.h>
#include <math.h>

// Problem constants
#define B_ 4
#define LQ_ 2048
#define LK_ 2048
#define DM_ 1024
#define NH_ 16
#define DK_ 64
#define DV_ 64
#define M_ (B_ * LQ_)          // 8192 rows for projection GEMMs

// ---------------- scratch (device globals: allocation-free rule) -----------
__device__ float g_Qh[B_ * NH_ * LQ_ * DK_];   // [b,h,l,d]
__device__ float g_Kh[B_ * NH_ * LK_ * DK_];
__device__ float g_Vh[B_ * NH_ * LK_ * DV_];
__device__ float g_Hout[M_ * (NH_ * DV_)];     // [b*l, h*dv] for FC GEMM

// ---------------- projection GEMM: C = A(8192x1024) @ W(1024x1024) + bias --
// blockIdx.z: 0=Q,1=K,2=V ; output written in head-split layout [b,h,l,d]
#define BM 64
#define BN 64
#define BKK 16

__global__ void proj_kernel(const float* __restrict__ q,
                            const float* __restrict__ k,
                            const float* __restrict__ v,
                            const float* __restrict__ wq, const float* __restrict__ bq,
                            const float* __restrict__ wk, const float* __restrict__ bk,
                            const float* __restrict__ wv, const float* __restrict__ bv)
{
    const int which = blockIdx.z;
    const float* A    = (which == 0) ? q  : (which == 1) ? k  : v;
    const float* W    = (which == 0) ? wq : (which == 1) ? wk : wv;
    const float* bias = (which == 0) ? bq : (which == 1) ? bk : bv;
    float* Out        = (which == 0) ? g_Qh : (which == 1) ? g_Kh : g_Vh;

    __shared__ float As[BKK][BM + 1];
    __shared__ float Ws[BKK][BN + 1];

    const int m0 = blockIdx.y * BM;
    const int n0 = blockIdx.x * BN;
    const int tid = threadIdx.x;
    const int tm = (tid / 16) * 4;
    const int tn = (tid % 16) * 4;

    float acc[4][4] = {};

    for (int k0 = 0; k0 < DM_; k0 += BKK) {
        // load A tile 64x16 (transposed into As[k][m])
        {
            int lr = tid >> 2;            // 0..63
            int lc = (tid & 3) * 4;       // 0,4,8,12
            float4 a4 = *(const float4*)&A[(size_t)(m0 + lr) * DM_ + k0 + lc];
            As[lc + 0][lr] = a4.x; As[lc + 1][lr] = a4.y;
            As[lc + 2][lr] = a4.z; As[lc + 3][lr] = a4.w;
        }
        // load W tile 16x64
        {
            int wr = tid >> 4;            // 0..15
            int wc = (tid & 15) * 4;
            float4 w4 = *(const float4*)&W[(size_t)(k0 + wr) * DM_ + n0 + wc];
            Ws[wr][wc + 0] = w4.x; Ws[wr][wc + 1] = w4.y;
            Ws[wr][wc + 2] = w4.z; Ws[wr][wc + 3] = w4.w;
        }
        __syncthreads();
        #pragma unroll
        for (int kk = 0; kk < BKK; kk++) {
            float a[4], w[4];
            #pragma unroll
            for (int i = 0; i < 4; i++) a[i] = As[kk][tm + i];
            #pragma unroll
            for (int j = 0; j < 4; j++) w[j] = Ws[kk][tn + j];
            #pragma unroll
            for (int i = 0; i < 4; i++)
                #pragma unroll
                for (int j = 0; j < 4; j++)
                    acc[i][j] += a[i] * w[j];
        }
        __syncthreads();
    }

    #pragma unroll
    for (int i = 0; i < 4; i++) {
        int m = m0 + tm + i;
        int b = m >> 11;            // /2048
        int l = m & 2047;
        #pragma unroll
        for (int j = 0; j < 4; j++) {
            int n = n0 + tn + j;
            int h = n >> 6;
            int d = n & 63;
            Out[(((size_t)(b * NH_ + h)) * LQ_ + l) * 64 + d] = acc[i][j] + bias[n];
        }
    }
}

// ---------------- FC GEMM + bias + residual -> d_out ----------------------
__global__ void fc_kernel(const float* __restrict__ fc_w,
                          const float* __restrict__ fc_b,
                          const float* __restrict__ q_in,
                          float* __restrict__ out)
{
    __shared__ float As[BKK][BM + 1];
    __shared__ float Ws[BKK][BN + 1];

    const int m0 = blockIdx.y * BM;
    const int n0 = blockIdx.x * BN;
    const int tid = threadIdx.x;
    const int tm = (tid / 16) * 4;
    const int tn = (tid % 16) * 4;

    float acc[4][4] = {};

    for (int k0 = 0; k0 < DM_; k0 += BKK) {
        {
            int lr = tid >> 2;
            int lc = (tid & 3) * 4;
            float4 a4 = *(const float4*)&g_Hout[(size_t)(m0 + lr) * DM_ + k0 + lc];
            As[lc + 0][lr] = a4.x; As[lc + 1][lr] = a4.y;
            As[lc + 2][lr] = a4.z; As[lc + 3][lr] = a4.w;
        }
        {
            int wr = tid >> 4;
            int wc = (tid & 15) * 4;
            float4 w4 = *(const float4*)&fc_w[(size_t)(k0 + wr) * DM_ + n0 + wc];
            Ws[wr][wc + 0] = w4.x; Ws[wr][wc + 1] = w4.y;
            Ws[wr][wc + 2] = w4.z; Ws[wr][wc + 3] = w4.w;
        }
        __syncthreads();
        #pragma unroll
        for (int kk = 0; kk < BKK; kk++) {
            float a[4], w[4];
            #pragma unroll
            for (int i = 0; i < 4; i++) a[i] = As[kk][tm + i];
            #pragma unroll
            for (int j = 0; j < 4; j++) w[j] = Ws[kk][tn + j];
            #pragma unroll
            for (int i = 0; i < 4; i++)
                #pragma unroll
                for (int j = 0; j < 4; j++)
                    acc[i][j] += a[i] * w[j];
        }
        __syncthreads();
    }

    #pragma unroll
    for (int i = 0; i < 4; i++) {
        int m = m0 + tm + i;
        #pragma unroll
        for (int j = 0; j < 4; j++) {
            int n = n0 + tn + j;
            size_t idx = (size_t)m * DM_ + n;
            out[idx] = acc[i][j] + fc_b[n] + q_in[idx];
        }
    }
}

// ---------------- attention: per (b,h,16 q-rows) --------------------------
// dyn smem: sS[16][2048] + sQ[16][64] + sKV[128][65]
#define QROWS 16
#define KCH 128
#define SKV_STRIDE 65

__global__ void attn_kernel(const int* __restrict__ mask,
                            float* __restrict__ attn_out,
                            int write_attn)
{
    extern __shared__ float smem[];
    float* sS  = smem;                        // 16*2048
    float* sQ  = sS + QROWS * LK_;            // 16*64
    float* sKV = sQ + QROWS * 64;             // 128*65

    const int b  = blockIdx.z;
    const int h  = blockIdx.y;
    const int q0 = blockIdx.x * QROWS;
    const int tid = threadIdx.x;      // 256
    const int tx = tid & 31, ty = tid >> 5;   // 8 warps

    const size_t headoff = ((size_t)(b * NH_ + h)) * (size_t)LK_ * 64;
    const float* Qbase = g_Qh + headoff + (size_t)q0 * 64;
    const float* Kbase = g_Kh + headoff;
    const float* Vbase = g_Vh + headoff;

    // load Q (scaled by 1/temperature = 1/8)
    for (int i = tid; i < QROWS * 64 / 4; i += 256) {
        float4 vq = ((const float4*)Qbase)[i];
        vq.x *= 0.125f; vq.y *= 0.125f; vq.z *= 0.125f; vq.w *= 0.125f;
        ((float4*)sQ)[i] = vq;
    }

    // ---- scores: sS = (Q/8) @ K^T ----
    for (int kc = 0; kc < LK_; kc += KCH) {
        __syncthreads();   // protect sKV reuse (also orders first-iter Q load)
        for (int i = tid; i < KCH * 16; i += 256) {    // 128 rows * 16 float4
            int r = i >> 4, c4 = i & 15;
            float4 vv = ((const float4*)(Kbase + (size_t)(kc + r) * 64))[c4];
            int o = r * SKV_STRIDE + c4 * 4;
            sKV[o] = vv.x; sKV[o + 1] = vv.y; sKV[o + 2] = vv.z; sKV[o + 3] = vv.w;
        }
        __syncthreads();

        float acc0[4] = {}, acc1[4] = {};
        const float* q0p = sQ + (2 * ty) * 64;
        const float* q1p = q0p + 64;
        #pragma unroll 8
        for (int d = 0; d < 64; d++) {
            float qa = q0p[d], qb = q1p[d];
            #pragma unroll
            for (int j = 0; j < 4; j++) {
                float kv = sKV[(tx + 32 * j) * SKV_STRIDE + d];
                acc0[j] += qa * kv;
                acc1[j] += qb * kv;
            }
        }
        #pragma unroll
        for (int j = 0; j < 4; j++) {
            sS[(2 * ty) * LK_ + kc + tx + 32 * j]     = acc0[j];
            sS[(2 * ty + 1) * LK_ + kc + tx + 32 * j] = acc1[j];
        }
    }
    __syncthreads();

    // ---- masked softmax per row, write attn output ----
    for (int rr = 0; rr < 2; rr++) {
        int row = ty * 2 + rr;
        const int* mrow = mask + ((size_t)b * LQ_ + q0 + row) * (size_t)LK_;
        float* srow = sS + (size_t)row * LK_;

        float mx = -INFINITY;
        for (int k = tx; k < LK_; k += 32) {
            float s = mrow[k] ? -INFINITY : srow[k];
            srow[k] = s;
            mx = fmaxf(mx, s);
        }
        #pragma unroll
        for (int o = 16; o; o >>= 1) mx = fmaxf(mx, __shfl_xor_sync(0xffffffffu, mx, o));

        float sum = 0.f;
        for (int k = tx; k < LK_; k += 32) {
            float e = __expf(srow[k] - mx);
            srow[k] = e;
            sum += e;
        }
        #pragma unroll
        for (int o = 16; o; o >>= 1) sum += __shfl_xor_sync(0xffffffffu, sum, o);
        float inv = 1.f / sum;

        float* arow = attn_out + (headoff * 32 /* (b*16+h)*2048*2048 */) + (size_t)(q0 + row) * LK_;
        for (int k = tx; k < LK_; k += 32) {
            float p = srow[k] * inv;
            srow[k] = p;
            if (write_attn) arow[k] = p;
        }
    }

    // ---- out = P @ V ----
    const int d  = tid & 63;
    const int qg = tid >> 6;     // 0..3 -> rows 4*qg..4*qg+3
    float acc4[4] = {};
    for (int vc = 0; vc < LK_; vc += KCH) {
        __syncthreads();
        for (int i = tid; i < KCH * 16; i += 256) {
            int r = i >> 4, c4 = i & 15;
            float4 vv = ((const float4*)(Vbase + (size_t)(vc + r) * 64))[c4];
            int o = r * SKV_STRIDE + c4 * 4;
            sKV[o] = vv.x; sKV[o + 1] = vv.y; sKV[o + 2] = vv.z; sKV[o + 3] = vv.w;
        }
        __syncthreads();
        #pragma unroll 4
        for (int kk = 0; kk < KCH; kk++) {
            float vv = sKV[kk * SKV_STRIDE + d];
            #pragma unroll
            for (int r = 0; r < 4; r++)
                acc4[r] += sS[(size_t)(qg * 4 + r) * LK_ + vc + kk] * vv;
        }
    }
    #pragma unroll
    for (int r = 0; r < 4; r++) {
        int qrow = qg * 4 + r;
        g_Hout[((size_t)b * LQ_ + q0 + qrow) * DM_ + h * 64 + d] = acc4[r];
    }
}

// ---------------- launch ---------------------------------------------------
extern "C" void kernel_launch(void* const* d_in, const int* in_sizes, int n_in,
                              void* d_out, int out_size)
{
    const float* q    = (const float*)d_in[0];
    const float* k    = (const float*)d_in[1];
    const float* v    = (const float*)d_in[2];
    const int*   mask = (const int*)d_in[3];          // bool delivered as int32
    const float* w_qs = (const float*)d_in[4];
    const float* b_qs = (const float*)d_in[5];
    const float* w_ks = (const float*)d_in[6];
    const float* b_ks = (const float*)d_in[7];
    const float* w_vs = (const float*)d_in[8];
    const float* b_vs = (const float*)d_in[9];
    const float* fc_w = (const float*)d_in[10];
    const float* fc_b = (const float*)d_in[11];

    float* out = (float*)d_out;
    const size_t out_elems = (size_t)M_ * DM_;                    // 8388608
    int write_attn = (out_size > (int)out_elems) ? 1 : 0;
    float* attn_out = out + out_elems;                            // tuple part 2

    // projections: Q,K,V
    {
        dim3 grid(DM_ / BN, M_ / BM, 3);
        proj_kernel<<<grid, 256>>>(q, k, v, w_qs, b_qs, w_ks, b_ks, w_vs, b_vs);
    }

    // attention
    {
        static int smem_set = 0;
        size_t smem = (size_t)(QROWS * LK_ + QROWS * 64 + KCH * SKV_STRIDE) * sizeof(float);
        if (!smem_set) {
            cudaFuncSetAttribute(attn_kernel, cudaFuncAttributeMaxDynamicSharedMemorySize, (int)smem);
            smem_set = 1;
        }
        dim3 grid(LQ_ / QROWS, NH_, B_);
        attn_kernel<<<grid, 256, smem>>>(mask, attn_out, write_attn);
    }

    // output projection + residual
    {
        dim3 grid(DM_ / BN, M_ / BM, 1);
        fc_kernel<<<grid, 256>>>(fc_w, fc_b, q, out);
    }
}

// round 3
// speedup vs baseline: 2.9780x; 2.9780x over previous
#include <cuda_runtime.h>
#include <cuda_bf16.h>
#include <math.h>
#include <stdint.h>

#define B_   4
#define LQ_  2048
#define LK_  2048
#define DM_  1024
#define NH_  16
#define M_   (B_*LQ_)

// ---------------- device scratch (allocation-free rule) --------------------
__device__ float  g_Qh[(size_t)B_*NH_*LQ_*64];
__device__ float  g_Kh[(size_t)B_*NH_*LK_*64];
__device__ float  g_Vh[(size_t)B_*NH_*LK_*64];
__device__ float  g_Hout[(size_t)M_*DM_];
__device__ float  g_mchunk[(size_t)B_*NH_*LQ_*16];
__device__ float2 g_rowstat[(size_t)B_*NH_*LQ_];

// ---------------- helpers --------------------------------------------------
__device__ __forceinline__ uint32_t pack_bf16(float x, float y){
    __nv_bfloat162 t = __floats2bfloat162_rn(x, y);
    return *reinterpret_cast<uint32_t*>(&t);
}
__device__ __forceinline__ void split_pack(float x0, float x1, uint32_t& h, uint32_t& l){
    float h0 = __bfloat162float(__float2bfloat16(x0));
    float h1 = __bfloat162float(__float2bfloat16(x1));
    h = pack_bf16(h0, h1);
    l = pack_bf16(x0 - h0, x1 - h1);
}
__device__ __forceinline__ void mma16816(float* c,
    uint32_t a0, uint32_t a1, uint32_t a2, uint32_t a3, uint32_t b0, uint32_t b1){
    asm volatile("mma.sync.aligned.m16n8k16.row.col.f32.bf16.bf16.f32 "
        "{%0,%1,%2,%3}, {%4,%5,%6,%7}, {%8,%9}, {%0,%1,%2,%3};"
        : "+f"(c[0]), "+f"(c[1]), "+f"(c[2]), "+f"(c[3])
        : "r"(a0), "r"(a1), "r"(a2), "r"(a3), "r"(b0), "r"(b1));
}

// ---------------- projection GEMM (split bf16, 3-mma) ----------------------
// C[8192,1024] = A @ W + bias -> head-split [b,h,l,d]
#define K2S  12        // padded uint32 stride per 16-k tile (8 pairs used)
#define TBUF (128*K2S) // 1536 u32 per tile buffer

__global__ void __launch_bounds__(256, 2) proj_kernel(
    const float* __restrict__ q, const float* __restrict__ k, const float* __restrict__ v,
    const float* __restrict__ wq, const float* __restrict__ bq,
    const float* __restrict__ wk, const float* __restrict__ bk,
    const float* __restrict__ wv, const float* __restrict__ bv)
{
    extern __shared__ uint32_t sm[];
    uint32_t* Ah = sm;
    uint32_t* Al = Ah + 2*TBUF;
    uint32_t* Bh = Al + 2*TBUF;
    uint32_t* Bl = Bh + 2*TBUF;

    const int which = blockIdx.z;
    const float* A    = which==0 ? q  : which==1 ? k  : v;
    const float* W    = which==0 ? wq : which==1 ? wk : wv;
    const float* bias = which==0 ? bq : which==1 ? bk : bv;
    float* Out        = which==0 ? g_Qh : which==1 ? g_Kh : g_Vh;

    const int m0 = blockIdx.y*128, n0 = blockIdx.x*128;
    const int tid = threadIdx.x, lane = tid & 31, wid = tid >> 5;
    const int wm = (wid & 3)*32, wn = (wid >> 2)*64;

    float acc[2][8][4];
    #pragma unroll
    for (int a=0;a<2;a++)
        #pragma unroll
        for (int b2=0;b2<8;b2++)
            #pragma unroll
            for (int c=0;c<4;c++) acc[a][b2][c]=0.f;

    float4 ra[2], rw[2];

    auto prefetch = [&](int k0){
        #pragma unroll
        for (int p=0;p<2;p++){
            int idx = tid + p*256;
            int m = idx>>2, k4 = (idx&3)<<2;
            ra[p] = *reinterpret_cast<const float4*>(A + (size_t)(m0+m)*DM_ + k0 + k4);
            int kk_ = idx>>5, n4 = (idx&31)<<2;
            rw[p] = *reinterpret_cast<const float4*>(W + (size_t)(k0+kk_)*DM_ + n0 + n4);
        }
    };
    auto commit = [&](int buf){
        uint32_t* ah = Ah + buf*TBUF; uint32_t* al = Al + buf*TBUF;
        __nv_bfloat16* bh16 = reinterpret_cast<__nv_bfloat16*>(Bh + buf*TBUF);
        __nv_bfloat16* bl16 = reinterpret_cast<__nv_bfloat16*>(Bl + buf*TBUF);
        #pragma unroll
        for (int p=0;p<2;p++){
            int idx = tid + p*256;
            int m = idx>>2, k4 = (idx&3)<<2;
            uint32_t h0,l0,h1,l1;
            split_pack(ra[p].x, ra[p].y, h0, l0);
            split_pack(ra[p].z, ra[p].w, h1, l1);
            int o = m*K2S + (k4>>1);
            ah[o]=h0; ah[o+1]=h1; al[o]=l0; al[o+1]=l1;
            int kk_ = idx>>5, n4 = (idx&31)<<2;
            float vv[4] = {rw[p].x, rw[p].y, rw[p].z, rw[p].w};
            #pragma unroll
            for (int i=0;i<4;i++){
                float hh = __bfloat162float(__float2bfloat16(vv[i]));
                bh16[(n4+i)*(K2S*2) + kk_] = __float2bfloat16(hh);
                bl16[(n4+i)*(K2S*2) + kk_] = __float2bfloat16(vv[i]-hh);
            }
        }
    };

    prefetch(0); commit(0); __syncthreads();
    int cur = 0;
    #pragma unroll 1
    for (int it=0; it<DM_/16; it++){
        if (it+1 < DM_/16) prefetch((it+1)*16);
        uint32_t* ah = Ah + cur*TBUF; uint32_t* al = Al + cur*TBUF;
        uint32_t* bh = Bh + cur*TBUF; uint32_t* bl = Bl + cur*TBUF;
        #pragma unroll
        for (int mt=0; mt<2; mt++){
            int ao = (wm + mt*16 + (lane>>2))*K2S + (lane&3);
            uint32_t a0h=ah[ao], a1h=ah[ao+8*K2S], a2h=ah[ao+4], a3h=ah[ao+8*K2S+4];
            uint32_t a0l=al[ao], a1l=al[ao+8*K2S], a2l=al[ao+4], a3l=al[ao+8*K2S+4];
            #pragma unroll
            for (int nt=0; nt<8; nt++){
                int bo = (wn + nt*8 + (lane>>2))*K2S + (lane&3);
                uint32_t b0h=bh[bo], b1h=bh[bo+4];
                uint32_t b0l=bl[bo], b1l=bl[bo+4];
                mma16816(acc[mt][nt], a0h,a1h,a2h,a3h, b0h,b1h);
                mma16816(acc[mt][nt], a0h,a1h,a2h,a3h, b0l,b1l);
                mma16816(acc[mt][nt], a0l,a1l,a2l,a3l, b0h,b1h);
            }
        }
        if (it+1 < DM_/16) commit(cur^1);
        __syncthreads();
        cur ^= 1;
    }

    #pragma unroll
    for (int mt=0; mt<2; mt++){
        int r0 = m0 + wm + mt*16 + (lane>>2);
        #pragma unroll
        for (int nt=0; nt<8; nt++){
            int col = n0 + wn + nt*8 + 2*(lane&3);
            float b0v = bias[col], b1v = bias[col+1];
            int hh = col>>6, dd = col&63;
            {
                int r = r0; int bb = r>>11, ll = r&2047;
                float2 val = make_float2(acc[mt][nt][0]+b0v, acc[mt][nt][1]+b1v);
                *reinterpret_cast<float2*>(Out + (((size_t)(bb*NH_+hh))*LQ_ + ll)*64 + dd) = val;
            }
            {
                int r = r0+8; int bb = r>>11, ll = r&2047;
                float2 val = make_float2(acc[mt][nt][2]+b0v, acc[mt][nt][3]+b1v);
                *reinterpret_cast<float2*>(Out + (((size_t)(bb*NH_+hh))*LQ_ + ll)*64 + dd) = val;
            }
        }
    }
}

// ---------------- FC GEMM (single bf16) + bias + residual ------------------
__global__ void __launch_bounds__(256, 2) fc_kernel(
    const float* __restrict__ fc_w, const float* __restrict__ fc_b,
    const float* __restrict__ q_in, float* __restrict__ out)
{
    extern __shared__ uint32_t sm[];
    uint32_t* Ah = sm;             // [2][TBUF]
    uint32_t* Bh = Ah + 2*TBUF;

    const int m0 = blockIdx.y*128, n0 = blockIdx.x*128;
    const int tid = threadIdx.x, lane = tid & 31, wid = tid >> 5;
    const int wm = (wid & 3)*32, wn = (wid >> 2)*64;

    float acc[2][8][4];
    #pragma unroll
    for (int a=0;a<2;a++)
        #pragma unroll
        for (int b2=0;b2<8;b2++)
            #pragma unroll
            for (int c=0;c<4;c++) acc[a][b2][c]=0.f;

    float4 ra[2], rw[2];
    auto prefetch = [&](int k0){
        #pragma unroll
        for (int p=0;p<2;p++){
            int idx = tid + p*256;
            int m = idx>>2, k4 = (idx&3)<<2;
            ra[p] = *reinterpret_cast<const float4*>(g_Hout + (size_t)(m0+m)*DM_ + k0 + k4);
            int kk_ = idx>>5, n4 = (idx&31)<<2;
            rw[p] = *reinterpret_cast<const float4*>(fc_w + (size_t)(k0+kk_)*DM_ + n0 + n4);
        }
    };
    auto commit = [&](int buf){
        uint32_t* ah = Ah + buf*TBUF;
        __nv_bfloat16* bh16 = reinterpret_cast<__nv_bfloat16*>(Bh + buf*TBUF);
        #pragma unroll
        for (int p=0;p<2;p++){
            int idx = tid + p*256;
            int m = idx>>2, k4 = (idx&3)<<2;
            int o = m*K2S + (k4>>1);
            ah[o]   = pack_bf16(ra[p].x, ra[p].y);
            ah[o+1] = pack_bf16(ra[p].z, ra[p].w);
            int kk_ = idx>>5, n4 = (idx&31)<<2;
            float vv[4] = {rw[p].x, rw[p].y, rw[p].z, rw[p].w};
            #pragma unroll
            for (int i=0;i<4;i++)
                bh16[(n4+i)*(K2S*2) + kk_] = __float2bfloat16(vv[i]);
        }
    };

    prefetch(0); commit(0); __syncthreads();
    int cur = 0;
    #pragma unroll 1
    for (int it=0; it<DM_/16; it++){
        if (it+1 < DM_/16) prefetch((it+1)*16);
        uint32_t* ah = Ah + cur*TBUF;
        uint32_t* bh = Bh + cur*TBUF;
        #pragma unroll
        for (int mt=0; mt<2; mt++){
            int ao = (wm + mt*16 + (lane>>2))*K2S + (lane&3);
            uint32_t a0=ah[ao], a1=ah[ao+8*K2S], a2=ah[ao+4], a3=ah[ao+8*K2S+4];
            #pragma unroll
            for (int nt=0; nt<8; nt++){
                int bo = (wn + nt*8 + (lane>>2))*K2S + (lane&3);
                mma16816(acc[mt][nt], a0,a1,a2,a3, bh[bo], bh[bo+4]);
            }
        }
        if (it+1 < DM_/16) commit(cur^1);
        __syncthreads();
        cur ^= 1;
    }

    #pragma unroll
    for (int mt=0; mt<2; mt++){
        int r0 = m0 + wm + mt*16 + (lane>>2);
        #pragma unroll
        for (int nt=0; nt<8; nt++){
            int col = n0 + wn + nt*8 + 2*(lane&3);
            float b0v = fc_b[col], b1v = fc_b[col+1];
            {
                size_t idx = (size_t)r0*DM_ + col;
                float2 res = *reinterpret_cast<const float2*>(q_in + idx);
                float2 val = make_float2(acc[mt][nt][0]+b0v+res.x, acc[mt][nt][1]+b1v+res.y);
                *reinterpret_cast<float2*>(out + idx) = val;
            }
            {
                size_t idx = (size_t)(r0+8)*DM_ + col;
                float2 res = *reinterpret_cast<const float2*>(q_in + idx);
                float2 val = make_float2(acc[mt][nt][2]+b0v+res.x, acc[mt][nt][3]+b1v+res.y);
                *reinterpret_cast<float2*>(out + idx) = val;
            }
        }
    }
}

// ---------------- attention: flash-style, writes p_tilde + stats -----------
// block = (b, h, 128 q-rows); 8 warps x 16 rows; k chunks of 128
#define QSTR 36     // u32 stride for [row][d-pair] tiles
#define VSTR 68     // u32 stride for V [d][kpos-pair]

__global__ void __launch_bounds__(256, 1) attn_kernel(
    const int* __restrict__ mask, float* __restrict__ attn_out)
{
    extern __shared__ uint32_t smha[];
    uint32_t* Qh = smha;                    // 128*36
    uint32_t* Ql = Qh + 128*QSTR;
    uint32_t* Kh = Ql + 128*QSTR;
    uint32_t* Kl = Kh + 128*QSTR;
    uint32_t* Vp = Kl + 128*QSTR;           // 64*68

    const int b  = blockIdx.z, h = blockIdx.y;
    const int q0 = blockIdx.x * 128;
    const int bh = b*NH_ + h;
    const int tid = threadIdx.x, lane = tid & 31, wid = tid >> 5;
    const int wrow = wid * 16;
    const size_t headoff = (size_t)bh * LK_ * 64;

    // load + scale + split Q tile [128][64]
    #pragma unroll
    for (int p=0; p<8; p++){
        int idx = tid + p*256;
        int m = idx >> 4, d4 = (idx & 15) << 2;
        float4 qv = *reinterpret_cast<const float4*>(g_Qh + headoff + (size_t)(q0+m)*64 + d4);
        qv.x *= 0.125f; qv.y *= 0.125f; qv.z *= 0.125f; qv.w *= 0.125f;
        uint32_t h0,l0,h1,l1;
        split_pack(qv.x, qv.y, h0, l0);
        split_pack(qv.z, qv.w, h1, l1);
        int o = m*QSTR + (d4>>1);
        Qh[o]=h0; Qh[o+1]=h1; Ql[o]=l0; Ql[o+1]=l1;
    }

    float mrow0 = -INFINITY, mrow1 = -INFINITY;
    float lrow0 = 0.f, lrow1 = 0.f;
    float o[8][4];
    #pragma unroll
    for (int t=0;t<8;t++){ o[t][0]=0.f;o[t][1]=0.f;o[t][2]=0.f;o[t][3]=0.f; }

    const int rbase = q0 + wrow + (lane>>2);

    #pragma unroll 1
    for (int kc=0; kc<LK_; kc+=128){
        __syncthreads();
        // K chunk -> split [kpos][d-pair]
        #pragma unroll
        for (int p=0;p<8;p++){
            int idx = tid + p*256;
            int kp = idx >> 4, d4 = (idx & 15) << 2;
            float4 kv = *reinterpret_cast<const float4*>(g_Kh + headoff + (size_t)(kc+kp)*64 + d4);
            uint32_t h0,l0,h1,l1;
            split_pack(kv.x,kv.y,h0,l0); split_pack(kv.z,kv.w,h1,l1);
            int oo = kp*QSTR + (d4>>1);
            Kh[oo]=h0; Kh[oo+1]=h1; Kl[oo]=l0; Kl[oo+1]=l1;
        }
        // V chunk -> bf16 [d][kpos]
        {
            __nv_bfloat16* v16 = reinterpret_cast<__nv_bfloat16*>(Vp);
            int d4 = tid >> 4;
            #pragma unroll
            for (int p=0;p<8;p++){
                int kp = (tid & 15) + p*16;
                float4 vv = *reinterpret_cast<const float4*>(g_Vh + headoff + (size_t)(kc+kp)*64 + d4*4);
                v16[(d4*4+0)*(VSTR*2) + kp] = __float2bfloat16(vv.x);
                v16[(d4*4+1)*(VSTR*2) + kp] = __float2bfloat16(vv.y);
                v16[(d4*4+2)*(VSTR*2) + kp] = __float2bfloat16(vv.z);
                v16[(d4*4+3)*(VSTR*2) + kp] = __float2bfloat16(vv.w);
            }
        }
        __syncthreads();

        // ---- S = (Q/8) @ K^T, split 3-mma ----
        float s[16][4];
        #pragma unroll
        for (int t=0;t<16;t++){ s[t][0]=0.f;s[t][1]=0.f;s[t][2]=0.f;s[t][3]=0.f; }
        #pragma unroll
        for (int ks=0; ks<4; ks++){
            int ao = (wrow + (lane>>2))*QSTR + ks*8 + (lane&3);
            uint32_t a0h=Qh[ao], a1h=Qh[ao+8*QSTR], a2h=Qh[ao+4], a3h=Qh[ao+8*QSTR+4];
            uint32_t a0l=Ql[ao], a1l=Ql[ao+8*QSTR], a2l=Ql[ao+4], a3l=Ql[ao+8*QSTR+4];
            #pragma unroll
            for (int nt=0; nt<16; nt++){
                int bo = (nt*8 + (lane>>2))*QSTR + ks*8 + (lane&3);
                uint32_t b0h=Kh[bo], b1h=Kh[bo+4];
                uint32_t b0l=Kl[bo], b1l=Kl[bo+4];
                mma16816(s[nt], a0h,a1h,a2h,a3h, b0h,b1h);
                mma16816(s[nt], a0h,a1h,a2h,a3h, b0l,b1l);
                mma16816(s[nt], a0l,a1l,a2l,a3l, b0h,b1h);
            }
        }

        // ---- mask + chunk max ----
        float cm0 = -INFINITY, cm1 = -INFINITY;
        const int* mr0 = mask + ((size_t)b*LQ_ + rbase)*LK_;
        const int* mr1 = mask + ((size_t)b*LQ_ + rbase + 8)*LK_;
        #pragma unroll
        for (int nt=0; nt<16; nt++){
            int col = kc + nt*8 + 2*(lane&3);
            int2 mv0 = *reinterpret_cast<const int2*>(mr0 + col);
            int2 mv1 = *reinterpret_cast<const int2*>(mr1 + col);
            if (mv0.x) s[nt][0] = -INFINITY;
            if (mv0.y) s[nt][1] = -INFINITY;
            if (mv1.x) s[nt][2] = -INFINITY;
            if (mv1.y) s[nt][3] = -INFINITY;
            cm0 = fmaxf(cm0, fmaxf(s[nt][0], s[nt][1]));
            cm1 = fmaxf(cm1, fmaxf(s[nt][2], s[nt][3]));
        }
        cm0 = fmaxf(cm0, __shfl_xor_sync(0xffffffffu, cm0, 1));
        cm0 = fmaxf(cm0, __shfl_xor_sync(0xffffffffu, cm0, 2));
        cm1 = fmaxf(cm1, __shfl_xor_sync(0xffffffffu, cm1, 1));
        cm1 = fmaxf(cm1, __shfl_xor_sync(0xffffffffu, cm1, 2));

        float mn0 = fmaxf(mrow0, cm0), mn1 = fmaxf(mrow1, cm1);
        float corr0 = (mrow0 == -INFINITY) ? 0.f : __expf(mrow0 - mn0);
        float corr1 = (mrow1 == -INFINITY) ? 0.f : __expf(mrow1 - mn1);

        // ---- p = exp(s - m_new), row sums ----
        float sum0 = 0.f, sum1 = 0.f;
        #pragma unroll
        for (int nt=0; nt<16; nt++){
            s[nt][0] = __expf(s[nt][0] - mn0);
            s[nt][1] = __expf(s[nt][1] - mn0);
            s[nt][2] = __expf(s[nt][2] - mn1);
            s[nt][3] = __expf(s[nt][3] - mn1);
            sum0 += s[nt][0] + s[nt][1];
            sum1 += s[nt][2] + s[nt][3];
        }
        sum0 += __shfl_xor_sync(0xffffffffu, sum0, 1);
        sum0 += __shfl_xor_sync(0xffffffffu, sum0, 2);
        sum1 += __shfl_xor_sync(0xffffffffu, sum1, 1);
        sum1 += __shfl_xor_sync(0xffffffffu, sum1, 2);

        lrow0 = lrow0*corr0 + sum0;
        lrow1 = lrow1*corr1 + sum1;
        mrow0 = mn0; mrow1 = mn1;

        // rescale O
        #pragma unroll
        for (int t=0;t<8;t++){
            o[t][0]*=corr0; o[t][1]*=corr0; o[t][2]*=corr1; o[t][3]*=corr1;
        }

        // write p_tilde + chunk max
        float* ar0 = attn_out + ((size_t)bh*LQ_ + rbase)*LK_;
        float* ar1 = ar0 + 8*(size_t)LK_;
        #pragma unroll
        for (int nt=0; nt<16; nt++){
            int col = kc + nt*8 + 2*(lane&3);
            __stcs(reinterpret_cast<float2*>(ar0 + col), make_float2(s[nt][0], s[nt][1]));
            __stcs(reinterpret_cast<float2*>(ar1 + col), make_float2(s[nt][2], s[nt][3]));
        }
        if ((lane & 3) == 0){
            g_mchunk[((size_t)bh*LQ_ + rbase)*16 + (kc>>7)]     = mn0;
            g_mchunk[((size_t)bh*LQ_ + rbase + 8)*16 + (kc>>7)] = mn1;
        }

        // ---- O += p_tilde @ V (single bf16) ----
        #pragma unroll
        for (int kk=0; kk<8; kk++){
            uint32_t a0 = pack_bf16(s[2*kk][0],   s[2*kk][1]);
            uint32_t a1 = pack_bf16(s[2*kk][2],   s[2*kk][3]);
            uint32_t a2 = pack_bf16(s[2*kk+1][0], s[2*kk+1][1]);
            uint32_t a3 = pack_bf16(s[2*kk+1][2], s[2*kk+1][3]);
            #pragma unroll
            for (int nt2=0; nt2<8; nt2++){
                int bo = (nt2*8 + (lane>>2))*VSTR + kk*8 + (lane&3);
                mma16816(o[nt2], a0,a1,a2,a3, Vp[bo], Vp[bo+4]);
            }
        }
    }

    // finalize O and stats
    float inv0 = 1.f / lrow0, inv1 = 1.f / lrow1;
    #pragma unroll
    for (int t=0;t<8;t++){
        o[t][0]*=inv0; o[t][1]*=inv0; o[t][2]*=inv1; o[t][3]*=inv1;
    }
    #pragma unroll
    for (int nt2=0; nt2<8; nt2++){
        int dcol = nt2*8 + 2*(lane&3);
        *reinterpret_cast<float2*>(g_Hout + ((size_t)b*LQ_ + rbase)*DM_ + h*64 + dcol)
            = make_float2(o[nt2][0], o[nt2][1]);
        *reinterpret_cast<float2*>(g_Hout + ((size_t)b*LQ_ + rbase + 8)*DM_ + h*64 + dcol)
            = make_float2(o[nt2][2], o[nt2][3]);
    }
    if ((lane & 3) == 0){
        g_rowstat[(size_t)bh*LQ_ + rbase]     = make_float2(mrow0, lrow0);
        g_rowstat[(size_t)bh*LQ_ + rbase + 8] = make_float2(mrow1, lrow1);
    }
}

// ---------------- rescale: p_final = p_tilde * exp(m_c - m_f) / l ----------
__global__ void rescale_kernel(float* __restrict__ attn)
{
    const int bh = blockIdx.y;
    const int qq = blockIdx.x;
    const size_t rowidx = (size_t)bh*LQ_ + qq;
    float2 st = g_rowstat[rowidx];
    int t = threadIdx.x;
    int chunk = t >> 4;
    float f = __expf(g_mchunk[rowidx*16 + chunk] - st.x) / st.y;
    float4* p = reinterpret_cast<float4*>(attn + rowidx*LK_ + t*8);
    float4 v0 = p[0], v1 = p[1];
    v0.x*=f; v0.y*=f; v0.z*=f; v0.w*=f;
    v1.x*=f; v1.y*=f; v1.z*=f; v1.w*=f;
    p[0] = v0; p[1] = v1;
}

// ---------------- launch ---------------------------------------------------
extern "C" void kernel_launch(void* const* d_in, const int* in_sizes, int n_in,
                              void* d_out, int out_size)
{
    const float* q    = (const float*)d_in[0];
    const float* k    = (const float*)d_in[1];
    const float* v    = (const float*)d_in[2];
    const int*   mask = (const int*)d_in[3];
    const float* w_qs = (const float*)d_in[4];
    const float* b_qs = (const float*)d_in[5];
    const float* w_ks = (const float*)d_in[6];
    const float* b_ks = (const float*)d_in[7];
    const float* w_vs = (const float*)d_in[8];
    const float* b_vs = (const float*)d_in[9];
    const float* fc_w = (const float*)d_in[10];
    const float* fc_b = (const float*)d_in[11];

    float* out = (float*)d_out;
    float* attn_out = out + (size_t)M_ * DM_;

    cudaFuncSetAttribute(proj_kernel, cudaFuncAttributeMaxDynamicSharedMemorySize, 8*TBUF*4);
    cudaFuncSetAttribute(fc_kernel,   cudaFuncAttributeMaxDynamicSharedMemorySize, 4*TBUF*4);
    cudaFuncSetAttribute(attn_kernel, cudaFuncAttributeMaxDynamicSharedMemorySize,
                         (4*128*QSTR + 64*VSTR)*4);

    proj_kernel<<<dim3(8, 64, 3), 256, 8*TBUF*4>>>(q, k, v, w_qs, b_qs, w_ks, b_ks, w_vs, b_vs);
    attn_kernel<<<dim3(16, NH_, B_), 256, (4*128*QSTR + 64*VSTR)*4>>>(mask, attn_out);
    rescale_kernel<<<dim3(LQ_, B_*NH_), 256>>>(attn_out);
    fc_kernel<<<dim3(8, 64), 256, 4*TBUF*4>>>(fc_w, fc_b, q, out);
}

// round 4
// speedup vs baseline: 4.4150x; 1.4825x over previous
#include <cuda_runtime.h>
#include <cuda_bf16.h>
#include <math.h>
#include <stdint.h>

#define B_   4
#define LQ_  2048
#define LK_  2048
#define DM_  1024
#define NH_  16
#define M_   8192

// ---------------- device scratch (allocation-free rule) --------------------
__device__ uint32_t g_Ih[3][4194304];     // split-hi of q,k,v inputs (bf16x2)
__device__ uint32_t g_Il[3][4194304];     // split-lo
__device__ uint32_t g_Wth[4][524288];     // transposed weights hi [n][k-pair]; idx3 = fc_w
__device__ uint32_t g_Wtl[3][524288];     // transposed weights lo
__device__ uint32_t g_Qhi[4194304], g_Qlo[4194304];   // [b,h,l,d-pair], pre-scaled 1/8
__device__ uint32_t g_Khi[4194304], g_Klo[4194304];
__device__ uint32_t g_Vh [4194304];
__device__ uint32_t g_Hbf[4194304];       // attn output bf16 [m][k-pair] for FC
__device__ uint32_t g_mbits[524288];      // mask bitwords [b][lq][lk/32]
__device__ float    g_mchunk[(size_t)B_*NH_*LQ_*16];
__device__ float2   g_rowstat[(size_t)B_*NH_*LQ_];

// ---------------- helpers --------------------------------------------------
__device__ __forceinline__ uint32_t pack_bf16(float x, float y){
    __nv_bfloat162 t = __floats2bfloat162_rn(x, y);
    return *reinterpret_cast<uint32_t*>(&t);
}
__device__ __forceinline__ void split_u32(float x0, float x1, uint32_t& h, uint32_t& l){
    float h0 = __bfloat162float(__float2bfloat16(x0));
    float h1 = __bfloat162float(__float2bfloat16(x1));
    h = pack_bf16(h0, h1);
    l = pack_bf16(x0 - h0, x1 - h1);
}
__device__ __forceinline__ void mma16816(float* c,
    uint32_t a0, uint32_t a1, uint32_t a2, uint32_t a3, uint32_t b0, uint32_t b1){
    asm volatile("mma.sync.aligned.m16n8k16.row.col.f32.bf16.bf16.f32 "
        "{%0,%1,%2,%3}, {%4,%5,%6,%7}, {%8,%9}, {%0,%1,%2,%3};"
        : "+f"(c[0]), "+f"(c[1]), "+f"(c[2]), "+f"(c[3])
        : "r"(a0), "r"(a1), "r"(a2), "r"(a3), "r"(b0), "r"(b1));
}
__device__ __forceinline__ void ldsm_x4(uint32_t* r, uint32_t addr){
    asm volatile("ldmatrix.sync.aligned.m8n8.x4.shared.b16 {%0,%1,%2,%3}, [%4];"
        : "=r"(r[0]), "=r"(r[1]), "=r"(r[2]), "=r"(r[3]) : "r"(addr));
}
__device__ __forceinline__ void cp_async16(uint32_t saddr, const void* gaddr){
    asm volatile("cp.async.cg.shared.global [%0], [%1], 16;" :: "r"(saddr), "l"(gaddr));
}
__device__ __forceinline__ void cp_commit(){ asm volatile("cp.async.commit_group;"); }
template<int N> __device__ __forceinline__ void cp_wait(){
    asm volatile("cp.async.wait_group %0;" :: "n"(N));
}
__device__ __forceinline__ uint32_t smem_u32addr(const void* p){
    uint32_t a;
    asm("{.reg .u64 t; cvta.to.shared.u64 t, %1; cvt.u32.u64 %0, t;}" : "=r"(a) : "l"(p));
    return a;
}

// ---------------- convert kernels ------------------------------------------
__global__ void k_split_inputs(const float* __restrict__ q,
                               const float* __restrict__ k,
                               const float* __restrict__ v){
    size_t F = (size_t)blockIdx.x*256 + threadIdx.x;   // float4 index
    int mat = (int)(F >> 21);
    size_t rem = F & 2097151u;
    const float* src = mat==0 ? q : mat==1 ? k : v;
    float4 a = reinterpret_cast<const float4*>(src)[rem];
    uint32_t h0,l0,h1,l1;
    split_u32(a.x, a.y, h0, l0);
    split_u32(a.z, a.w, h1, l1);
    g_Ih[mat][rem*2]   = h0; g_Ih[mat][rem*2+1] = h1;
    g_Il[mat][rem*2]   = l0; g_Il[mat][rem*2+1] = l1;
}

__global__ void k_conv_w(const float* __restrict__ wq, const float* __restrict__ wk,
                         const float* __restrict__ wv, const float* __restrict__ fcw){
    const int mat = blockIdx.z;
    const float* W = mat==0 ? wq : mat==1 ? wk : mat==2 ? wv : fcw;
    __shared__ float T[32][33];
    const int k0 = blockIdx.y*32, n0 = blockIdx.x*32;
    const int tx = threadIdx.x & 31, ty = threadIdx.x >> 5;
    #pragma unroll
    for (int i=0;i<4;i++)
        T[ty+8*i][tx] = W[(size_t)(k0+ty+8*i)*DM_ + n0 + tx];
    __syncthreads();
    const int n = threadIdx.x >> 3;
    const int kp0 = (threadIdx.x & 7)*2;
    #pragma unroll
    for (int s2=0;s2<2;s2++){
        int kp = kp0 + s2;                     // k-pair within tile (0..15)
        float x0 = T[kp*2][n], x1 = T[kp*2+1][n];
        uint32_t h, l; split_u32(x0, x1, h, l);
        size_t o = (size_t)(n0+n)*512 + (k0>>1) + kp;
        g_Wth[mat][o] = h;
        if (mat < 3) g_Wtl[mat][o] = l;
    }
}

__global__ void k_mask_bits(const int* __restrict__ mask){
    int wrp = blockIdx.x*8 + (threadIdx.x>>5);
    int lane = threadIdx.x & 31;
    size_t base = (size_t)wrp*32;
    for (int j=0;j<32;j++){
        size_t w = base + j;
        int mv = mask[w*32 + lane];
        uint32_t bits = __ballot_sync(0xffffffffu, mv != 0);
        if (lane==0) g_mbits[w] = bits;
    }
}

// ---------------- projection GEMM ------------------------------------------
// 128x128 tile, k16 stages x4, cp.async + ldmatrix + 3-mma split
#define PSTG 6144            // u32 per stage (4 buffers x 1536)
#define BUFB 6144            // bytes per buffer

__global__ void __launch_bounds__(256,2) proj_kernel(
    const float* __restrict__ bq, const float* __restrict__ bk,
    const float* __restrict__ bv)
{
    extern __shared__ uint32_t smp[];
    const uint32_t sbase = smem_u32addr(smp);

    const int which = blockIdx.z;
    const uint32_t* gAh = g_Ih[which];
    const uint32_t* gAl = g_Il[which];
    const uint32_t* gBh = g_Wth[which];
    const uint32_t* gBl = g_Wtl[which];
    const float* bias = which==0 ? bq : which==1 ? bk : bv;

    const int m0 = blockIdx.y*128, n0 = blockIdx.x*128;
    const int tid = threadIdx.x, lane = tid & 31, wid = tid >> 5;
    const int wm = (wid & 3)*32, wn = (wid >> 2)*64;

    const int crow = tid >> 1, chalf = tid & 1;
    const uint32_t* gsrc0 = gAh + (size_t)(m0+crow)*512 + chalf*4;
    const uint32_t* gsrc1 = gAl + (size_t)(m0+crow)*512 + chalf*4;
    const uint32_t* gsrc2 = gBh + (size_t)(n0+crow)*512 + chalf*4;
    const uint32_t* gsrc3 = gBl + (size_t)(n0+crow)*512 + chalf*4;
    const uint32_t sdst = sbase + crow*48 + chalf*16;

    auto issue = [&](int itk){
        int stage = itk & 3;
        uint32_t so = sdst + stage*(PSTG*4);
        size_t ko = (size_t)itk*8;
        cp_async16(so + 0*BUFB, gsrc0 + ko);
        cp_async16(so + 1*BUFB, gsrc1 + ko);
        cp_async16(so + 2*BUFB, gsrc2 + ko);
        cp_async16(so + 3*BUFB, gsrc3 + ko);
        cp_commit();
    };

    float acc[2][8][4];
    #pragma unroll
    for (int a=0;a<2;a++)
        #pragma unroll
        for (int b2=0;b2<8;b2++){ acc[a][b2][0]=0.f;acc[a][b2][1]=0.f;acc[a][b2][2]=0.f;acc[a][b2][3]=0.f; }

    issue(0); issue(1); issue(2);

    const uint32_t arow = wm + (lane & 15);
    const uint32_t aoff0 = arow*48 + ((lane>>4)&1)*16;
    const uint32_t brow = wn + (lane & 7) + ((lane & 16) ? 8 : 0);
    const uint32_t boff0 = 2*BUFB + brow*48 + ((lane & 8) ? 16 : 0);

    #pragma unroll 1
    for (int it=0; it<64; it++){
        if (it <= 61) cp_wait<2>(); else if (it == 62) cp_wait<1>(); else cp_wait<0>();
        __syncthreads();
        if (it + 3 < 64) issue(it+3);

        uint32_t sb = sbase + (it & 3)*(PSTG*4);
        uint32_t a_h[2][4], a_l[2][4];
        ldsm_x4(a_h[0], sb + aoff0);
        ldsm_x4(a_h[1], sb + aoff0 + 16*48);
        ldsm_x4(a_l[0], sb + aoff0 + BUFB);
        ldsm_x4(a_l[1], sb + aoff0 + BUFB + 16*48);
        #pragma unroll
        for (int p=0;p<4;p++){
            uint32_t bh4[4], bl4[4];
            ldsm_x4(bh4, sb + boff0 + p*16*48);
            ldsm_x4(bl4, sb + boff0 + BUFB + p*16*48);
            #pragma unroll
            for (int mt=0;mt<2;mt++){
                mma16816(acc[mt][2*p],   a_h[mt][0],a_h[mt][1],a_h[mt][2],a_h[mt][3], bh4[0],bh4[1]);
                mma16816(acc[mt][2*p+1], a_h[mt][0],a_h[mt][1],a_h[mt][2],a_h[mt][3], bh4[2],bh4[3]);
            }
            #pragma unroll
            for (int mt=0;mt<2;mt++){
                mma16816(acc[mt][2*p],   a_h[mt][0],a_h[mt][1],a_h[mt][2],a_h[mt][3], bl4[0],bl4[1]);
                mma16816(acc[mt][2*p+1], a_h[mt][0],a_h[mt][1],a_h[mt][2],a_h[mt][3], bl4[2],bl4[3]);
            }
            #pragma unroll
            for (int mt=0;mt<2;mt++){
                mma16816(acc[mt][2*p],   a_l[mt][0],a_l[mt][1],a_l[mt][2],a_l[mt][3], bh4[0],bh4[1]);
                mma16816(acc[mt][2*p+1], a_l[mt][0],a_l[mt][1],a_l[mt][2],a_l[mt][3], bh4[2],bh4[3]);
            }
        }
    }

    const float sc = (which==0) ? 0.125f : 1.0f;
    #pragma unroll
    for (int mt=0;mt<2;mt++){
        int r0 = m0 + wm + mt*16 + (lane>>2);
        #pragma unroll
        for (int nt=0;nt<8;nt++){
            int col = n0 + wn + nt*8 + 2*(lane&3);
            float2 bv2 = *reinterpret_cast<const float2*>(bias + col);
            int hh = col>>6, dd = col&63;
            #pragma unroll
            for (int rr=0;rr<2;rr++){
                int r = r0 + rr*8;
                int bb2 = r>>11, ll = r&2047;
                size_t o = (((size_t)(bb2*NH_+hh))*LQ_ + ll)*32 + (dd>>1);
                float x0 = (acc[mt][nt][rr*2]   + bv2.x)*sc;
                float x1 = (acc[mt][nt][rr*2+1] + bv2.y)*sc;
                uint32_t h, l; split_u32(x0, x1, h, l);
                if (which==0){ g_Qhi[o]=h; g_Qlo[o]=l; }
                else if (which==1){ g_Khi[o]=h; g_Klo[o]=l; }
                else { g_Vh[o]=h; }
            }
        }
    }
}

// ---------------- FC GEMM + bias + residual --------------------------------
#define FSTG 3072

__global__ void __launch_bounds__(256,2) fc_kernel(
    const float* __restrict__ fc_b, const float* __restrict__ q_in,
    float* __restrict__ out)
{
    extern __shared__ uint32_t smf[];
    const uint32_t sbase = smem_u32addr(smf);

    const int m0 = blockIdx.y*128, n0 = blockIdx.x*128;
    const int tid = threadIdx.x, lane = tid & 31, wid = tid >> 5;
    const int wm = (wid & 3)*32, wn = (wid >> 2)*64;

    const int crow = tid >> 1, chalf = tid & 1;
    const uint32_t* gsrc0 = g_Hbf    + (size_t)(m0+crow)*512 + chalf*4;
    const uint32_t* gsrc1 = g_Wth[3] + (size_t)(n0+crow)*512 + chalf*4;
    const uint32_t sdst = sbase + crow*48 + chalf*16;

    auto issue = [&](int itk){
        int stage = itk & 3;
        uint32_t so = sdst + stage*(FSTG*4);
        size_t ko = (size_t)itk*8;
        cp_async16(so,        gsrc0 + ko);
        cp_async16(so + BUFB, gsrc1 + ko);
        cp_commit();
    };

    float acc[2][8][4];
    #pragma unroll
    for (int a=0;a<2;a++)
        #pragma unroll
        for (int b2=0;b2<8;b2++){ acc[a][b2][0]=0.f;acc[a][b2][1]=0.f;acc[a][b2][2]=0.f;acc[a][b2][3]=0.f; }

    issue(0); issue(1); issue(2);

    const uint32_t arow = wm + (lane & 15);
    const uint32_t aoff0 = arow*48 + ((lane>>4)&1)*16;
    const uint32_t brow = wn + (lane & 7) + ((lane & 16) ? 8 : 0);
    const uint32_t boff0 = BUFB + brow*48 + ((lane & 8) ? 16 : 0);

    #pragma unroll 1
    for (int it=0; it<64; it++){
        if (it <= 61) cp_wait<2>(); else if (it == 62) cp_wait<1>(); else cp_wait<0>();
        __syncthreads();
        if (it + 3 < 64) issue(it+3);

        uint32_t sb = sbase + (it & 3)*(FSTG*4);
        uint32_t a_h[2][4];
        ldsm_x4(a_h[0], sb + aoff0);
        ldsm_x4(a_h[1], sb + aoff0 + 16*48);
        #pragma unroll
        for (int p=0;p<4;p++){
            uint32_t bh4[4];
            ldsm_x4(bh4, sb + boff0 + p*16*48);
            #pragma unroll
            for (int mt=0;mt<2;mt++){
                mma16816(acc[mt][2*p],   a_h[mt][0],a_h[mt][1],a_h[mt][2],a_h[mt][3], bh4[0],bh4[1]);
                mma16816(acc[mt][2*p+1], a_h[mt][0],a_h[mt][1],a_h[mt][2],a_h[mt][3], bh4[2],bh4[3]);
            }
        }
    }

    #pragma unroll
    for (int mt=0;mt<2;mt++){
        int r0 = m0 + wm + mt*16 + (lane>>2);
        #pragma unroll
        for (int nt=0;nt<8;nt++){
            int col = n0 + wn + nt*8 + 2*(lane&3);
            float2 bv2 = *reinterpret_cast<const float2*>(fc_b + col);
            #pragma unroll
            for (int rr=0;rr<2;rr++){
                size_t idx = (size_t)(r0+rr*8)*DM_ + col;
                float2 res = *reinterpret_cast<const float2*>(q_in + idx);
                *reinterpret_cast<float2*>(out + idx) =
                    make_float2(acc[mt][nt][rr*2]+bv2.x+res.x, acc[mt][nt][rr*2+1]+bv2.y+res.y);
            }
        }
    }
}

// ---------------- attention -----------------------------------------------
#define QSTR 36
#define VSTR 68
// smem u32 offsets
#define OF_QH 0
#define OF_QL 4608
#define OF_KH 9216
#define OF_KL 13824
#define OF_VP 18432
#define ATTN_SMEM_U32 (18432+4352)

__global__ void __launch_bounds__(256,1) attn_kernel(float* __restrict__ attn_out)
{
    extern __shared__ uint32_t smq[];
    const uint32_t sbase = smem_u32addr(smq);
    uint32_t* Qh = smq;
    uint32_t* Ql = smq + OF_QL;
    uint32_t* Kh = smq + OF_KH;
    uint32_t* Kl = smq + OF_KL;
    uint32_t* Vp = smq + OF_VP;

    const int b  = blockIdx.z, h = blockIdx.y;
    const int q0 = blockIdx.x * 128;
    const int bh = b*NH_ + h;
    const int tid = threadIdx.x, lane = tid & 31, wid = tid >> 5;
    const int wrow = wid * 16;
    const size_t ho32 = (size_t)bh * LK_ * 32;   // u32 per head

    // Q tile (pre-scaled, pre-split)
    #pragma unroll
    for (int p=0;p<4;p++){
        int item = tid + p*256;
        int row = item>>3, o = item&7;
        *reinterpret_cast<uint4*>(Qh + row*QSTR + o*4) =
            *reinterpret_cast<const uint4*>(g_Qhi + ho32 + (size_t)(q0+row)*32 + o*4);
        *reinterpret_cast<uint4*>(Ql + row*QSTR + o*4) =
            *reinterpret_cast<const uint4*>(g_Qlo + ho32 + (size_t)(q0+row)*32 + o*4);
    }

    float mrow0 = -INFINITY, mrow1 = -INFINITY;
    float lrow0 = 0.f, lrow1 = 0.f;
    float o_[8][4];
    #pragma unroll
    for (int t=0;t<8;t++){ o_[t][0]=0.f;o_[t][1]=0.f;o_[t][2]=0.f;o_[t][3]=0.f; }

    const int rbase = q0 + wrow + (lane>>2);
    const uint32_t* mbits_row0 = g_mbits + ((size_t)b*LQ_ + rbase)*64;

    const uint32_t aaddr = sbase + (wrow + (lane&15))*144 + ((lane&16)?16:0);
    const uint32_t baddr = sbase + OF_KH*4 + ((lane&7) + ((lane&16)?8:0))*144 + ((lane&8)?16:0);
    const uint32_t vaddr = sbase + OF_VP*4 + ((lane&7) + ((lane&16)?8:0))*272 + ((lane&8)?16:0);

    #pragma unroll 1
    for (int kc=0; kc<LK_; kc+=128){
        __syncthreads();
        // K chunk
        #pragma unroll
        for (int p=0;p<4;p++){
            int item = tid + p*256;
            int row = item>>3, oo = item&7;
            *reinterpret_cast<uint4*>(Kh + row*QSTR + oo*4) =
                *reinterpret_cast<const uint4*>(g_Khi + ho32 + (size_t)(kc+row)*32 + oo*4);
            *reinterpret_cast<uint4*>(Kl + row*QSTR + oo*4) =
                *reinterpret_cast<const uint4*>(g_Klo + ho32 + (size_t)(kc+row)*32 + oo*4);
        }
        // V chunk transpose [kpos][d] -> [d][kpos-pair]
        #pragma unroll
        for (int p=0;p<2;p++){
            int item = tid + p*256;
            int kp = item>>3, oo = item&7;
            const uint32_t* src = g_Vh + ho32 + (size_t)(kc + 2*kp)*32 + oo*4;
            uint4 A = *reinterpret_cast<const uint4*>(src);
            uint4 Bv = *reinterpret_cast<const uint4*>(src + 32);
            const uint32_t* Ap = reinterpret_cast<const uint32_t*>(&A);
            const uint32_t* Bp = reinterpret_cast<const uint32_t*>(&Bv);
            #pragma unroll
            for (int jj=0;jj<4;jj++){
                int j = (jj + oo) & 3;
                int d0 = oo*8 + 2*j;
                Vp[d0*VSTR + kp]     = __byte_perm(Ap[j], Bp[j], 0x5410);
                Vp[(d0+1)*VSTR + kp] = __byte_perm(Ap[j], Bp[j], 0x7632);
            }
        }
        __syncthreads();

        // ---- S = Q' K^T (3-mma split) ----
        float s[16][4];
        #pragma unroll
        for (int t=0;t<16;t++){ s[t][0]=0.f;s[t][1]=0.f;s[t][2]=0.f;s[t][3]=0.f; }
        #pragma unroll
        for (int ks=0; ks<4; ks++){
            uint32_t ah[4], al[4];
            ldsm_x4(ah, aaddr + ks*32);
            ldsm_x4(al, aaddr + OF_QL*4 - OF_QH*4 + ks*32);
            #pragma unroll
            for (int p=0;p<8;p++){
                uint32_t bh4[4], bl4[4];
                ldsm_x4(bh4, baddr + p*16*144 + ks*32);
                ldsm_x4(bl4, baddr + (OF_KL-OF_KH)*4 + p*16*144 + ks*32);
                mma16816(s[2*p],   ah[0],ah[1],ah[2],ah[3], bh4[0],bh4[1]);
                mma16816(s[2*p+1], ah[0],ah[1],ah[2],ah[3], bh4[2],bh4[3]);
                mma16816(s[2*p],   ah[0],ah[1],ah[2],ah[3], bl4[0],bl4[1]);
                mma16816(s[2*p+1], ah[0],ah[1],ah[2],ah[3], bl4[2],bl4[3]);
                mma16816(s[2*p],   al[0],al[1],al[2],al[3], bh4[0],bh4[1]);
                mma16816(s[2*p+1], al[0],al[1],al[2],al[3], bh4[2],bh4[3]);
            }
        }

        // ---- mask (bitwords) + chunk max ----
        uint32_t mw0[4], mw1[4];
        #pragma unroll
        for (int c2=0;c2<4;c2++){
            mw0[c2] = mbits_row0[(kc>>5) + c2];
            mw1[c2] = mbits_row0[8*64 + (kc>>5) + c2];
        }
        float cm0 = -INFINITY, cm1 = -INFINITY;
        #pragma unroll
        for (int nt=0;nt<16;nt++){
            uint32_t w0 = mw0[nt>>2], w1 = mw1[nt>>2];
            int bsh = ((nt&3)<<3) + ((lane&3)<<1);
            if ((w0>>bsh)&1)     s[nt][0] = -INFINITY;
            if ((w0>>(bsh+1))&1) s[nt][1] = -INFINITY;
            if ((w1>>bsh)&1)     s[nt][2] = -INFINITY;
            if ((w1>>(bsh+1))&1) s[nt][3] = -INFINITY;
            cm0 = fmaxf(cm0, fmaxf(s[nt][0], s[nt][1]));
            cm1 = fmaxf(cm1, fmaxf(s[nt][2], s[nt][3]));
        }
        cm0 = fmaxf(cm0, __shfl_xor_sync(0xffffffffu, cm0, 1));
        cm0 = fmaxf(cm0, __shfl_xor_sync(0xffffffffu, cm0, 2));
        cm1 = fmaxf(cm1, __shfl_xor_sync(0xffffffffu, cm1, 1));
        cm1 = fmaxf(cm1, __shfl_xor_sync(0xffffffffu, cm1, 2));

        float mn0 = fmaxf(mrow0, cm0), mn1 = fmaxf(mrow1, cm1);
        float corr0 = (mrow0 == -INFINITY) ? 0.f : __expf(mrow0 - mn0);
        float corr1 = (mrow1 == -INFINITY) ? 0.f : __expf(mrow1 - mn1);

        float sum0 = 0.f, sum1 = 0.f;
        #pragma unroll
        for (int nt=0;nt<16;nt++){
            s[nt][0] = __expf(s[nt][0] - mn0);
            s[nt][1] = __expf(s[nt][1] - mn0);
            s[nt][2] = __expf(s[nt][2] - mn1);
            s[nt][3] = __expf(s[nt][3] - mn1);
            sum0 += s[nt][0] + s[nt][1];
            sum1 += s[nt][2] + s[nt][3];
        }
        sum0 += __shfl_xor_sync(0xffffffffu, sum0, 1);
        sum0 += __shfl_xor_sync(0xffffffffu, sum0, 2);
        sum1 += __shfl_xor_sync(0xffffffffu, sum1, 1);
        sum1 += __shfl_xor_sync(0xffffffffu, sum1, 2);

        lrow0 = lrow0*corr0 + sum0;
        lrow1 = lrow1*corr1 + sum1;
        mrow0 = mn0; mrow1 = mn1;

        #pragma unroll
        for (int t=0;t<8;t++){
            o_[t][0]*=corr0; o_[t][1]*=corr0; o_[t][2]*=corr1; o_[t][3]*=corr1;
        }

        // write p_tilde + chunk max
        float* ar0 = attn_out + ((size_t)bh*LQ_ + rbase)*LK_;
        float* ar1 = ar0 + 8*(size_t)LK_;
        #pragma unroll
        for (int nt=0;nt<16;nt++){
            int col = kc + nt*8 + 2*(lane&3);
            __stcs(reinterpret_cast<float2*>(ar0 + col), make_float2(s[nt][0], s[nt][1]));
            __stcs(reinterpret_cast<float2*>(ar1 + col), make_float2(s[nt][2], s[nt][3]));
        }
        if ((lane & 3) == 0){
            g_mchunk[((size_t)bh*LQ_ + rbase)*16 + (kc>>7)]     = mn0;
            g_mchunk[((size_t)bh*LQ_ + rbase + 8)*16 + (kc>>7)] = mn1;
        }

        // ---- O += p_tilde @ V ----
        #pragma unroll
        for (int kk=0;kk<8;kk++){
            uint32_t a0 = pack_bf16(s[2*kk][0],   s[2*kk][1]);
            uint32_t a1 = pack_bf16(s[2*kk][2],   s[2*kk][3]);
            uint32_t a2 = pack_bf16(s[2*kk+1][0], s[2*kk+1][1]);
            uint32_t a3 = pack_bf16(s[2*kk+1][2], s[2*kk+1][3]);
            #pragma unroll
            for (int g=0; g<4; g++){
                uint32_t bv4[4];
                ldsm_x4(bv4, vaddr + g*16*272 + kk*32);
                mma16816(o_[2*g],   a0,a1,a2,a3, bv4[0],bv4[1]);
                mma16816(o_[2*g+1], a0,a1,a2,a3, bv4[2],bv4[3]);
            }
        }
    }

    float inv0 = 1.f / lrow0, inv1 = 1.f / lrow1;
    #pragma unroll
    for (int nt2=0;nt2<8;nt2++){
        int dcol = nt2*8 + 2*(lane&3);
        size_t ro = ((size_t)b*LQ_ + rbase)*512 + h*32 + (dcol>>1);
        g_Hbf[ro]         = pack_bf16(o_[nt2][0]*inv0, o_[nt2][1]*inv0);
        g_Hbf[ro + 8*512] = pack_bf16(o_[nt2][2]*inv1, o_[nt2][3]*inv1);
    }
    if ((lane & 3) == 0){
        g_rowstat[(size_t)bh*LQ_ + rbase]     = make_float2(mrow0, lrow0);
        g_rowstat[(size_t)bh*LQ_ + rbase + 8] = make_float2(mrow1, lrow1);
    }
}

// ---------------- rescale ---------------------------------------------------
__global__ void rescale_kernel(float* __restrict__ attn)
{
    const int bh = blockIdx.y;
    const int qq = blockIdx.x;
    const size_t rowidx = (size_t)bh*LQ_ + qq;
    float2 st = g_rowstat[rowidx];
    int t = threadIdx.x;
    int chunk = t >> 4;
    float f = __expf(g_mchunk[rowidx*16 + chunk] - st.x) / st.y;
    float4* p = reinterpret_cast<float4*>(attn + rowidx*LK_ + t*8);
    float4 v0 = p[0], v1 = p[1];
    v0.x*=f; v0.y*=f; v0.z*=f; v0.w*=f;
    v1.x*=f; v1.y*=f; v1.z*=f; v1.w*=f;
    p[0] = v0; p[1] = v1;
}

// ---------------- launch ----------------------------------------------------
extern "C" void kernel_launch(void* const* d_in, const int* in_sizes, int n_in,
                              void* d_out, int out_size)
{
    const float* q    = (const float*)d_in[0];
    const float* k    = (const float*)d_in[1];
    const float* v    = (const float*)d_in[2];
    const int*   mask = (const int*)d_in[3];
    const float* b_qs = (const float*)d_in[5];
    const float* b_ks = (const float*)d_in[7];
    const float* b_vs = (const float*)d_in[9];
    const float* fc_w = (const float*)d_in[10];
    const float* fc_b = (const float*)d_in[11];
    const float* w_qs = (const float*)d_in[4];
    const float* w_ks = (const float*)d_in[6];
    const float* w_vs = (const float*)d_in[8];

    float* out = (float*)d_out;
    float* attn_out = out + (size_t)M_ * DM_;

    cudaFuncSetAttribute(proj_kernel, cudaFuncAttributeMaxDynamicSharedMemorySize, 4*PSTG*4);
    cudaFuncSetAttribute(fc_kernel,   cudaFuncAttributeMaxDynamicSharedMemorySize, 4*FSTG*4);
    cudaFuncSetAttribute(attn_kernel, cudaFuncAttributeMaxDynamicSharedMemorySize, ATTN_SMEM_U32*4);

    k_split_inputs<<<24576, 256>>>(q, k, v);
    k_conv_w<<<dim3(32,32,4), 256>>>(w_qs, w_ks, w_vs, fc_w);
    k_mask_bits<<<2048, 256>>>(mask);

    proj_kernel<<<dim3(8,64,3), 256, 4*PSTG*4>>>(b_qs, b_ks, b_vs);
    attn_kernel<<<dim3(16,NH_,B_), 256, ATTN_SMEM_U32*4>>>(attn_out);
    rescale_kernel<<<dim3(LQ_, B_*NH_), 256>>>(attn_out);
    fc_kernel<<<dim3(8,64), 256, 4*FSTG*4>>>(fc_b, q, out);
}